// round 5
// baseline (speedup 1.0000x reference)
#include <cuda_runtime.h>
#include <cstdint>

#define NB 4
#define LSEQ 16384
#define CCH 64
#define CM 16
#define NH 4
#define HB 128
#define KCH 128
#define JTOT (NH*LSEQ)
#define NKEY 640
#define TILE 128
#define NTILE (JTOT/TILE)   // 512
#define TL 64

typedef unsigned long long ull;
typedef unsigned int uint32;

// ---------------- device scratch ----------------
__device__ __align__(16) float g_xembed[NB][LSEQ][CM];
__device__ __align__(16) float g_yembed[NB][LSEQ][CCH];
__device__ float g_xnorm[NB][LSEQ];
__device__ float g_invn[NB][LSEQ];
__device__ int   g_codes[NB][JTOT];
__device__ int   g_perm[NB][JTOT];
__device__ int   g_tileHist[NB][NTILE][NKEY];   // zeroed at load; re-zeroed by k_combine
__device__ int   g_keyBase[NB][NKEY];
__device__ __align__(16) unsigned short g_ret[NB][JTOT][CCH];   // bf16
__device__ float g_bs[NB][JTOT];

// ---------------- helpers ----------------
__device__ __forceinline__ float ex2a(float t){
    float r; asm("ex2.approx.f32 %0,%1;" : "=f"(r) : "f"(t)); return r;
}
__device__ __forceinline__ float lg2a(float t){
    float r; asm("lg2.approx.f32 %0,%1;" : "=f"(r) : "f"(t)); return r;
}
__device__ __forceinline__ uint32 pkbf(float lo, float hi){
    uint32 r; asm("cvt.rn.bf16x2.f32 %0, %1, %2;" : "=r"(r) : "f"(hi), "f"(lo)); return r;
}
__device__ __forceinline__ unsigned short bfr(float x){
    unsigned short r; asm("cvt.rn.bf16.f32 %0,%1;" : "=h"(r) : "f"(x)); return r;
}
__device__ __forceinline__ float blo(uint32 u){ return __uint_as_float(u << 16); }
__device__ __forceinline__ float bhi(uint32 u){ return __uint_as_float(u & 0xffff0000u); }

__device__ __forceinline__ void mma16816(float* d, const uint32* a, uint32 b0, uint32 b1){
    asm volatile("mma.sync.aligned.m16n8k16.row.col.f32.bf16.bf16.f32 "
        "{%0,%1,%2,%3},{%4,%5,%6,%7},{%8,%9},{%0,%1,%2,%3};"
        : "+f"(d[0]), "+f"(d[1]), "+f"(d[2]), "+f"(d[3])
        : "r"(a[0]), "r"(a[1]), "r"(a[2]), "r"(a[3]), "r"(b0), "r"(b1));
}

#define LOG2E 1.4426950408889634f
#define LN2   0.6931471805599453f

// ---------------- K0: fused embed + hash + hist (register-blocked) ----------------
// smem layout (float words):
#define EH_SXT 0                    // sxT [64][67]  (c, r) transposed x
#define EH_SWM 4288                 // swm [192][16]
#define EH_SWA (4288+3072)          // swa [64][64]  (c, o)
#define EH_SWB (4288+3072+4096)     // swb [64]
#define EH_SR  (4288+3072+4096+64)  // sR  [512][16]
#define EH_SXE (EH_SR+8192)         // sxe [64][20]
#define EH_TOT (EH_SXE+1280)
#define SMEM_EHH (EH_TOT*4)

__global__ void __launch_bounds__(256) k_ehh(
        const float* __restrict__ x, const float* __restrict__ wm,
        const float* __restrict__ wa, const float* __restrict__ wb,
        const float* __restrict__ rot){
    extern __shared__ float sm[];
    float* sxT = sm + EH_SXT;
    float* swm = sm + EH_SWM;
    float* swa = sm + EH_SWA;
    float* swb = sm + EH_SWB;
    float* sR  = sm + EH_SR;
    float* sxe = sm + EH_SXE;

    int b = blockIdx.x;
    int n = b / (LSEQ/TL);
    int l0 = (b % (LSEQ/TL)) * TL;
    int tid = threadIdx.x;

    // stage x transposed: sxT[c*67 + r] = x[l0+r-1][c], r in [0,66)
    for (int idx = tid; idx < 66*64; idx += 256){
        int r = idx >> 6, c = idx & 63;
        int l = l0 + r - 1;
        sxT[c*67 + r] = (l >= 0 && l < LSEQ) ? x[((size_t)n*LSEQ + l)*64 + c] : 0.f;
    }
    for (int idx = tid; idx < 3072; idx += 256){
        int f = idx / 192, rem = idx % 192;
        swm[rem*16 + f] = wm[idx];
    }
    for (int idx = tid; idx < 4096; idx += 256){
        int o = idx >> 6, c = idx & 63;
        swa[c*64 + o] = wa[idx];
    }
    if (tid < 64) swb[tid] = wb[tid];
    for (int idx = tid; idx < 8192; idx += 256){
        int f = idx >> 9, hi = idx & 511;
        sR[hi*16 + f] = rot[idx];
    }
    __syncthreads();

    // x_embed: thread -> (lr, fb): 4 features for one row
    {
        int lr = tid >> 2, fb = (tid & 3)*4;
        float a0=0.f, a1=0.f, a2=0.f, a3=0.f;
        #pragma unroll 4
        for (int c = 0; c < 64; c++){
            #pragma unroll
            for (int tap = 0; tap < 3; tap++){
                float xv = sxT[c*67 + lr + tap];
                const float4 w4 = *(const float4*)&swm[(c*3+tap)*16 + fb];
                a0 = fmaf(xv, w4.x, a0);
                a1 = fmaf(xv, w4.y, a1);
                a2 = fmaf(xv, w4.z, a2);
                a3 = fmaf(xv, w4.w, a3);
            }
        }
        float4 r; r.x=a0; r.y=a1; r.z=a2; r.w=a3;
        *(float4*)&g_xembed[n][l0+lr][fb] = r;
        *(float4*)&sxe[lr*20 + fb] = r;
    }
    // y_embed: thread -> (ly, ob): 8 outputs, two row-halves
    {
        int ly = tid >> 3, ob = (tid & 7)*8;
        #pragma unroll
        for (int half = 0; half < 2; half++){
            int ll = half*32 + ly;
            float4 acc0 = *(const float4*)&swb[ob];
            float4 acc1 = *(const float4*)&swb[ob+4];
            #pragma unroll 8
            for (int c = 0; c < 64; c++){
                float xv = sxT[c*67 + ll + 1];
                const float4 w0 = *(const float4*)&swa[c*64 + ob];
                const float4 w1 = *(const float4*)&swa[c*64 + ob + 4];
                acc0.x = fmaf(xv, w0.x, acc0.x); acc0.y = fmaf(xv, w0.y, acc0.y);
                acc0.z = fmaf(xv, w0.z, acc0.z); acc0.w = fmaf(xv, w0.w, acc0.w);
                acc1.x = fmaf(xv, w1.x, acc1.x); acc1.y = fmaf(xv, w1.y, acc1.y);
                acc1.z = fmaf(xv, w1.z, acc1.z); acc1.w = fmaf(xv, w1.w, acc1.w);
            }
            *(float4*)&g_yembed[n][l0+ll][ob]   = acc0;
            *(float4*)&g_yembed[n][l0+ll][ob+4] = acc1;
        }
    }
    __syncthreads();

    // hash: thread = (h, ll)
    int h = tid >> 6, ll = tid & 63;
    int l = l0 + ll;
    float4 q0 = *(const float4*)&sxe[ll*20 + 0];
    float4 q1 = *(const float4*)&sxe[ll*20 + 4];
    float4 q2 = *(const float4*)&sxe[ll*20 + 8];
    float4 q3 = *(const float4*)&sxe[ll*20 + 12];

    if (h == 0){
        float nn = q0.x*q0.x + q0.y*q0.y + q0.z*q0.z + q0.w*q0.w;
        nn += q1.x*q1.x + q1.y*q1.y + q1.z*q1.z + q1.w*q1.w;
        nn += q2.x*q2.x + q2.y*q2.y + q2.z*q2.z + q2.w*q2.w;
        nn += q3.x*q3.x + q3.y*q3.y + q3.z*q3.z + q3.w*q3.w;
        nn = sqrtf(nn);
        g_xnorm[n][l] = nn;
        g_invn[n][l]  = 1.f / fmaxf(nn, 5e-5f);
    }
    float m1 = -1e30f, m2 = 1e30f; int i1 = 0, i2 = 0;
    const float* Rh = &sR[(h*128)*16];
    #pragma unroll 2
    for (int i = 0; i < 128; i++){
        const float4 r0 = *(const float4*)&Rh[i*16 + 0];
        const float4 r1 = *(const float4*)&Rh[i*16 + 4];
        const float4 r2 = *(const float4*)&Rh[i*16 + 8];
        const float4 r3 = *(const float4*)&Rh[i*16 + 12];
        float v = q0.x*r0.x + q0.y*r0.y + q0.z*r0.z + q0.w*r0.w;
        v += q1.x*r1.x + q1.y*r1.y + q1.z*r1.z + q1.w*r1.w;
        v += q2.x*r2.x + q2.y*r2.y + q2.z*r2.z + q2.w*r2.w;
        v += q3.x*r3.x + q3.y*r3.y + q3.z*r3.z + q3.w*r3.w;
        if (v > m1){ m1 = v; i1 = i; }
        if (v < m2){ m2 = v; i2 = i; }
    }
    int code = ((m1 >= -m2) ? i1 : (HB + i2)) + h*HB;
    int j = h*LSEQ + l;
    g_codes[n][j] = code;
    atomicAdd(&g_tileHist[n][j >> 7][code], 1);
}

// ---------------- K1: fused tile-prefix (per-key warp scans) + key base ----------------
__global__ void k_scan(){
    __shared__ int stot[NKEY];
    __shared__ int sc[1024];
    int n = blockIdx.x;
    int tid = threadIdx.x;
    int w = tid >> 5, lane = tid & 31;

    // phase 1: per-key scan over 512 tiles; one warp per key
    for (int k = w; k < NKEY; k += 32){
        int vals[16];
        int tl0 = lane*16;
        #pragma unroll
        for (int u = 0; u < 16; u++) vals[u] = g_tileHist[n][tl0+u][k];
        int s = 0;
        #pragma unroll
        for (int u = 0; u < 16; u++){ int t = vals[u]; vals[u] = s; s += t; }
        int run = s;
        #pragma unroll
        for (int off = 1; off < 32; off <<= 1){
            int o = __shfl_up_sync(0xffffffffu, run, off);
            if (lane >= off) run += o;
        }
        int excl = run - s;
        #pragma unroll
        for (int u = 0; u < 16; u++) g_tileHist[n][tl0+u][k] = vals[u] + excl;
        if (lane == 31) stot[k] = run;
    }
    __syncthreads();

    // phase 2: exclusive prefix over 640 key totals
    int v0 = (tid < NKEY) ? stot[tid] : 0;
    sc[tid] = v0;
    __syncthreads();
    #pragma unroll
    for (int off = 1; off < 1024; off <<= 1){
        int add = (tid >= off) ? sc[tid-off] : 0;
        __syncthreads();
        sc[tid] += add;
        __syncthreads();
    }
    if (tid < NKEY) g_keyBase[n][tid] = sc[tid] - v0;
}

// ---------------- K2: stable scatter (match_any + per-warp hist) ----------------
__global__ void __launch_bounds__(TILE) k_scatter(){
    __shared__ int shist[4][NKEY];
    int b = blockIdx.x; int n = b >> 9, tl = b & 511;
    int t = threadIdx.x;
    int w = t >> 5, lane = t & 31;
    for (int idx = t; idx < 4*NKEY; idx += TILE) ((int*)shist)[idx] = 0;
    __syncthreads();
    int key = g_codes[n][tl*TILE + t];
    atomicAdd(&shist[w][key], 1);
    unsigned mask = __match_any_sync(0xffffffffu, key);
    int r = __popc(mask & ((1u << lane) - 1u));
    __syncthreads();
    #pragma unroll
    for (int w2 = 0; w2 < 3; w2++)
        if (w2 < w) r += shist[w2][key];
    int pos = g_keyBase[n][key] + g_tileHist[n][tl][key] + r;
    g_perm[n][pos] = tl*TILE + t;
}

// ---------------- K3: chunked attention, bf16 tensor cores, per-pass staging ----------------
// smem (uint32 words): sQ[128][12]=1536  sK[128][12]=1536  sVT[64][68]=4352  sM2[128]  sJ[128]
#define AT_SQ 0
#define AT_SK 1536
#define AT_SVT 3072
#define AT_SM2 (3072+4352)
#define AT_SJ  (3072+4352+128)
#define SMEM_ATTN ((AT_SJ+128)*4)

__global__ void __launch_bounds__(128,4) k_attn(){
    extern __shared__ uint32 smw[];
    uint32* sQ = smw + AT_SQ;
    uint32* sK = smw + AT_SK;
    uint32* sVT32 = smw + AT_SVT;                       // [64][68] words
    unsigned short* sVT = (unsigned short*)sVT32;       // [64][136] uint16
    float* sM2 = (float*)(smw + AT_SM2);
    int*   sJ  = (int*)(smw + AT_SJ);

    int cid = blockIdx.x;
    int n = cid >> 9, rem = cid & 511;
    int g = rem >> 7, k = rem & 127;
    int tid = threadIdx.x;
    int lane = tid & 31, w = tid >> 5;
    int g4 = lane >> 2, t4 = lane & 3;
    int rbase = w*32;

    uint32 qf[2][4];
    float m2lo[2], m2hi[2];
    float o[2][8][4];
    #pragma unroll
    for (int rt = 0; rt < 2; rt++)
        #pragma unroll
        for (int ct = 0; ct < 8; ct++)
            #pragma unroll
            for (int u = 0; u < 4; u++) o[rt][ct][u] = 0.f;
    float rs0[2] = {0.f, 0.f}, rs1[2] = {0.f, 0.f};

    #pragma unroll
    for (int pass = 0; pass < 3; pass++){
        int kc = (pass == 0) ? k : (pass == 1) ? ((k + 127) & 127) : ((k + 1) & 127);
        __syncthreads();
        {
            int p = (g << 14) + (kc << 7) + tid;
            int j = g_perm[n][p];
            int l = j & (LSEQ - 1);
            float inv = g_invn[n][l];
            const float4* xp = (const float4*)&g_xembed[n][l][0];
            float4 a = xp[0], bb = xp[1], c = xp[2], d = xp[3];
            uint32* kr = &sK[tid*12];
            kr[0] = pkbf(a.x*inv, a.y*inv);  kr[1] = pkbf(a.z*inv, a.w*inv);
            kr[2] = pkbf(bb.x*inv, bb.y*inv); kr[3] = pkbf(bb.z*inv, bb.w*inv);
            kr[4] = pkbf(c.x*inv, c.y*inv);  kr[5] = pkbf(c.z*inv, c.w*inv);
            kr[6] = pkbf(d.x*inv, d.y*inv);  kr[7] = pkbf(d.z*inv, d.w*inv);
            if (pass == 0){
                sJ[tid] = j;
                sM2[tid] = g_xnorm[n][l] * LOG2E;
                uint32* qr = &sQ[tid*12];
                qr[0] = pkbf(a.x*LOG2E, a.y*LOG2E);  qr[1] = pkbf(a.z*LOG2E, a.w*LOG2E);
                qr[2] = pkbf(bb.x*LOG2E, bb.y*LOG2E); qr[3] = pkbf(bb.z*LOG2E, bb.w*LOG2E);
                qr[4] = pkbf(c.x*LOG2E, c.y*LOG2E);  qr[5] = pkbf(c.z*LOG2E, c.w*LOG2E);
                qr[6] = pkbf(d.x*LOG2E, d.y*LOG2E);  qr[7] = pkbf(d.z*LOG2E, d.w*LOG2E);
            }
            const float4* vp = (const float4*)&g_yembed[n][l][0];
            #pragma unroll
            for (int t = 0; t < 16; t++){
                float4 v = vp[t];
                sVT[(4*t+0)*136 + tid] = bfr(v.x);
                sVT[(4*t+1)*136 + tid] = bfr(v.y);
                sVT[(4*t+2)*136 + tid] = bfr(v.z);
                sVT[(4*t+3)*136 + tid] = bfr(v.w);
            }
        }
        __syncthreads();
        if (pass == 0){
            #pragma unroll
            for (int rt = 0; rt < 2; rt++){
                int row = rbase + rt*16 + g4;
                qf[rt][0] = sQ[row*12 + t4];
                qf[rt][1] = sQ[(row+8)*12 + t4];
                qf[rt][2] = sQ[row*12 + 4 + t4];
                qf[rt][3] = sQ[(row+8)*12 + 4 + t4];
                m2lo[rt] = sM2[row];
                m2hi[rt] = sM2[row+8];
            }
        }

        for (int nt = 0; nt < 8; nt++){
            uint32 kb[2][2];
            #pragma unroll
            for (int h = 0; h < 2; h++){
                int key = nt*16 + h*8 + g4;
                kb[h][0] = sK[key*12 + t4];
                kb[h][1] = sK[key*12 + 4 + t4];
            }
            float sc2[2][2][4];
            #pragma unroll
            for (int rt = 0; rt < 2; rt++)
                #pragma unroll
                for (int h = 0; h < 2; h++){
                    sc2[rt][h][0] = 0.f; sc2[rt][h][1] = 0.f;
                    sc2[rt][h][2] = 0.f; sc2[rt][h][3] = 0.f;
                    mma16816(sc2[rt][h], qf[rt], kb[h][0], kb[h][1]);
                }
            uint32 pf[2][4];
            #pragma unroll
            for (int rt = 0; rt < 2; rt++){
                #pragma unroll
                for (int h = 0; h < 2; h++){
                    float e0 = ex2a(sc2[rt][h][0] - m2lo[rt]);
                    float e1 = ex2a(sc2[rt][h][1] - m2lo[rt]);
                    float e2 = ex2a(sc2[rt][h][2] - m2hi[rt]);
                    float e3 = ex2a(sc2[rt][h][3] - m2hi[rt]);
                    rs0[rt] += e0 + e1;
                    rs1[rt] += e2 + e3;
                    pf[rt][h*2]   = pkbf(e0, e1);
                    pf[rt][h*2+1] = pkbf(e2, e3);
                }
            }
            #pragma unroll
            for (int ct = 0; ct < 8; ct++){
                int ch = ct*8 + g4;
                uint32 vb0 = sVT32[ch*68 + nt*8 + t4];
                uint32 vb1 = sVT32[ch*68 + nt*8 + 4 + t4];
                mma16816(o[0][ct], pf[0], vb0, vb1);
                mma16816(o[1][ct], pf[1], vb0, vb1);
            }
        }
    }

    // ---- epilogue ----
    #pragma unroll
    for (int rt = 0; rt < 2; rt++){
        float v0 = rs0[rt];
        v0 += __shfl_xor_sync(0xffffffffu, v0, 1);
        v0 += __shfl_xor_sync(0xffffffffu, v0, 2);
        float v1 = rs1[rt];
        v1 += __shfl_xor_sync(0xffffffffu, v1, 1);
        v1 += __shfl_xor_sync(0xffffffffu, v1, 2);
        float i0 = 1.f / v0, i1 = 1.f / v1;
        int row0 = rbase + rt*16 + g4, row1 = row0 + 8;
        int j0 = sJ[row0], j1 = sJ[row1];
        if (t4 == 0){
            g_bs[n][j0] = (sM2[row0] + lg2a(v0)) * LN2;
            g_bs[n][j1] = (sM2[row1] + lg2a(v1)) * LN2;
        }
        unsigned short* r0p = &g_ret[n][j0][0];
        unsigned short* r1p = &g_ret[n][j1][0];
        #pragma unroll
        for (int ct = 0; ct < 8; ct++){
            int ch = ct*8 + 2*t4;
            *(uint32*)&r0p[ch] = pkbf(o[rt][ct][0]*i0, o[rt][ct][1]*i0);
            *(uint32*)&r1p[ch] = pkbf(o[rt][ct][2]*i1, o[rt][ct][3]*i1);
        }
    }
}

// ---------------- K4: combine + residual + hist re-zero ----------------
__global__ void k_combine(const float* __restrict__ x, float* __restrict__ out){
    int gt = blockIdx.x * 256 + threadIdx.x;
    int n = gt >> 14, l = gt & (LSEQ - 1);
    float b0 = g_bs[n][l];
    float b1 = g_bs[n][LSEQ + l];
    float b2 = g_bs[n][2*LSEQ + l];
    float b3 = g_bs[n][3*LSEQ + l];
    float mx = fmaxf(fmaxf(b0, b1), fmaxf(b2, b3));
    float e0 = ex2a((b0 - mx)*LOG2E), e1 = ex2a((b1 - mx)*LOG2E);
    float e2 = ex2a((b2 - mx)*LOG2E), e3 = ex2a((b3 - mx)*LOG2E);
    float inv = 1.f / (e0 + e1 + e2 + e3);
    float p0 = e0*inv, p1 = e1*inv, p2 = e2*inv, p3 = e3*inv;

    const uint4* r0 = (const uint4*)&g_ret[n][l][0];
    const uint4* r1 = (const uint4*)&g_ret[n][LSEQ + l][0];
    const uint4* r2 = (const uint4*)&g_ret[n][2*LSEQ + l][0];
    const uint4* r3 = (const uint4*)&g_ret[n][3*LSEQ + l][0];
    const float4* x4 = (const float4*)&x[((size_t)n*LSEQ + l)*64];
    float4* o4 = (float4*)&out[((size_t)n*LSEQ + l)*64];
    #pragma unroll
    for (int t = 0; t < 8; t++){
        uint4 u0 = r0[t], u1 = r1[t], u2 = r2[t], u3 = r3[t];
        float4 xa = x4[2*t], xb = x4[2*t+1];
        float4 oa, ob;
        oa.x = xa.x + p0*blo(u0.x) + p1*blo(u1.x) + p2*blo(u2.x) + p3*blo(u3.x);
        oa.y = xa.y + p0*bhi(u0.x) + p1*bhi(u1.x) + p2*bhi(u2.x) + p3*bhi(u3.x);
        oa.z = xa.z + p0*blo(u0.y) + p1*blo(u1.y) + p2*blo(u2.y) + p3*blo(u3.y);
        oa.w = xa.w + p0*bhi(u0.y) + p1*bhi(u1.y) + p2*bhi(u2.y) + p3*bhi(u3.y);
        ob.x = xb.x + p0*blo(u0.z) + p1*blo(u1.z) + p2*blo(u2.z) + p3*blo(u3.z);
        ob.y = xb.y + p0*bhi(u0.z) + p1*bhi(u1.z) + p2*bhi(u2.z) + p3*bhi(u3.z);
        ob.z = xb.z + p0*blo(u0.w) + p1*blo(u1.w) + p2*blo(u2.w) + p3*blo(u3.w);
        ob.w = xb.w + p0*bhi(u0.w) + p1*bhi(u1.w) + p2*bhi(u2.w) + p3*bhi(u3.w);
        o4[2*t] = oa;
        o4[2*t+1] = ob;
    }
    int* hist = &g_tileHist[0][0][0];
    const int tot = NB*NTILE*NKEY;
    for (int idx = gt; idx < tot; idx += NB*LSEQ) hist[idx] = 0;
}

// ---------------- launch ----------------
extern "C" void kernel_launch(void* const* d_in, const int* in_sizes, int n_in,
                              void* d_out, int out_size){
    const float* x  = (const float*)d_in[0];
    const float* wm = (const float*)d_in[1];
    const float* wa = (const float*)d_in[2];
    const float* wb = (const float*)d_in[3];
    const float* rt = (const float*)d_in[4];
    float* out = (float*)d_out;

    static bool attr_done = false;
    if (!attr_done){
        cudaFuncSetAttribute(k_ehh, cudaFuncAttributeMaxDynamicSharedMemorySize, SMEM_EHH);
        attr_done = true;
    }

    k_ehh    <<<NB*(LSEQ/TL), 256, SMEM_EHH>>>(x, wm, wa, wb, rt);
    k_scan   <<<NB, 1024>>>();
    k_scatter<<<NB*NTILE, TILE>>>();
    k_attn   <<<NB*NH*KCH, 128, SMEM_ATTN>>>();
    k_combine<<<(NB*LSEQ)/256, 256>>>(x, out);
}

// round 6
// speedup vs baseline: 2.3712x; 2.3712x over previous
#include <cuda_runtime.h>
#include <cstdint>

#define NB 4
#define LSEQ 16384
#define CCH 64
#define CM 16
#define NH 4
#define HB 128
#define KCH 128
#define JTOT (NH*LSEQ)
#define NKEY 640
#define TILE 512
#define NTILE (JTOT/TILE)   // 128
#define TL 64

typedef unsigned long long ull;
typedef unsigned int uint32;

// ---------------- device scratch ----------------
__device__ __align__(16) float g_xembed[NB][LSEQ][CM];
__device__ __align__(16) float g_yembed[NB][LSEQ][CCH];
__device__ float g_xnorm[NB][LSEQ];
__device__ float g_invn[NB][LSEQ];
__device__ int   g_codes[NB][JTOT];
__device__ int   g_perm[NB][JTOT];
__device__ int   g_tileHist[NB][NTILE][NKEY];   // zeroed at load; re-zeroed by k_combine
__device__ int   g_keyBase[NB][NKEY];
__device__ __align__(16) unsigned short g_ret[NB][JTOT][CCH];   // bf16
__device__ float g_bs[NB][JTOT];

// ---------------- helpers ----------------
__device__ __forceinline__ float ex2a(float t){
    float r; asm("ex2.approx.f32 %0,%1;" : "=f"(r) : "f"(t)); return r;
}
__device__ __forceinline__ float lg2a(float t){
    float r; asm("lg2.approx.f32 %0,%1;" : "=f"(r) : "f"(t)); return r;
}
__device__ __forceinline__ uint32 pkbf(float lo, float hi){
    uint32 r; asm("cvt.rn.bf16x2.f32 %0, %1, %2;" : "=r"(r) : "f"(hi), "f"(lo)); return r;
}
__device__ __forceinline__ unsigned short bfr(float x){
    unsigned short r; asm("cvt.rn.bf16.f32 %0,%1;" : "=h"(r) : "f"(x)); return r;
}
__device__ __forceinline__ float blo(uint32 u){ return __uint_as_float(u << 16); }
__device__ __forceinline__ float bhi(uint32 u){ return __uint_as_float(u & 0xffff0000u); }

__device__ __forceinline__ void mma16816(float* d, const uint32* a, uint32 b0, uint32 b1){
    asm volatile("mma.sync.aligned.m16n8k16.row.col.f32.bf16.bf16.f32 "
        "{%0,%1,%2,%3},{%4,%5,%6,%7},{%8,%9},{%0,%1,%2,%3};"
        : "+f"(d[0]), "+f"(d[1]), "+f"(d[2]), "+f"(d[3])
        : "r"(a[0]), "r"(a[1]), "r"(a[2]), "r"(a[3]), "r"(b0), "r"(b1));
}

#define LOG2E 1.4426950408889634f
#define LN2   0.6931471805599453f

// ---------------- K0: fused embed + hash + hist (ROUND-4 VERSION) ----------------
#define OFF_SX   0
#define OFF_SWM  4224
#define OFF_SWA  (4224+3072)
#define OFF_SWB  (4224+3072+4096)
#define OFF_SXE  (4224+3072+4096+64)
#define OFF_SR   (4224+3072+4096+64+1088)
#define SMEM_EHH ((OFF_SR+8192)*4)

__global__ void k_ehh(const float* __restrict__ x, const float* __restrict__ wm,
                      const float* __restrict__ wa, const float* __restrict__ wb,
                      const float* __restrict__ rot){
    extern __shared__ float sm[];
    float (*sx)[64]  = (float(*)[64])(sm + OFF_SX);
    float (*swm)[16] = (float(*)[16])(sm + OFF_SWM);
    float (*swa)[64] = (float(*)[64])(sm + OFF_SWA);
    float *swb       = sm + OFF_SWB;
    float (*sxe)[17] = (float(*)[17])(sm + OFF_SXE);
    float (*sR)[16]  = (float(*)[16])(sm + OFF_SR);

    int b = blockIdx.x;
    int n = b / (LSEQ/TL);
    int l0 = (b % (LSEQ/TL)) * TL;
    int tid = threadIdx.x;

    for (int idx = tid; idx < (TL+2)*64; idx += 256){
        int r = idx >> 6, c = idx & 63;
        int l = l0 + r - 1;
        sx[r][c] = (l >= 0 && l < LSEQ) ? x[((size_t)n*LSEQ + l)*64 + c] : 0.f;
    }
    for (int idx = tid; idx < 3072; idx += 256){
        int f = idx / 192, rem = idx % 192;
        swm[rem][f] = wm[idx];
    }
    for (int idx = tid; idx < 4096; idx += 256){
        int o = idx >> 6, c = idx & 63;
        swa[c][o] = wa[idx];
    }
    if (tid < 64) swb[tid] = wb[tid];
    for (int idx = tid; idx < 8192; idx += 256){
        int f = idx >> 9, hi = idx & 511;
        sR[hi][f] = rot[idx];
    }
    __syncthreads();

    for (int idx = tid; idx < TL*16; idx += 256){
        int lr = idx >> 4, f = idx & 15;
        float acc = 0.f;
        #pragma unroll 8
        for (int c = 0; c < 64; c++){
            acc = fmaf(sx[lr  ][c], swm[c*3+0][f], acc);
            acc = fmaf(sx[lr+1][c], swm[c*3+1][f], acc);
            acc = fmaf(sx[lr+2][c], swm[c*3+2][f], acc);
        }
        g_xembed[n][l0+lr][f] = acc;
        sxe[lr][f] = acc;
    }
    for (int idx = tid; idx < TL*64; idx += 256){
        int lr = idx >> 6, o = idx & 63;
        float acc = swb[o];
        #pragma unroll 8
        for (int c = 0; c < 64; c++)
            acc = fmaf(sx[lr+1][c], swa[c][o], acc);
        g_yembed[n][l0+lr][o] = acc;
    }
    __syncthreads();

    int h = tid >> 6, ll = tid & 63;
    int l = l0 + ll;
    float q[16];
    #pragma unroll
    for (int f = 0; f < 16; f++) q[f] = sxe[ll][f];

    if (h == 0){
        float nn = 0.f;
        #pragma unroll
        for (int f = 0; f < 16; f++) nn = fmaf(q[f], q[f], nn);
        nn = sqrtf(nn);
        g_xnorm[n][l] = nn;
        g_invn[n][l]  = 1.f / fmaxf(nn, 5e-5f);
    }
    float m1 = -1e30f, m2 = 1e30f; int i1 = 0, i2 = 0;
    const float (*Rh)[16] = &sR[h*128];
    for (int i = 0; i < 128; i++){
        float v = 0.f;
        #pragma unroll
        for (int f = 0; f < 16; f++) v = fmaf(q[f], Rh[i][f], v);
        if (v > m1){ m1 = v; i1 = i; }
        if (v < m2){ m2 = v; i2 = i; }
    }
    int code = ((m1 >= -m2) ? i1 : (HB + i2)) + h*HB;
    int j = h*LSEQ + l;
    g_codes[n][j] = code;
    atomicAdd(&g_tileHist[n][j >> 9][code], 1);
}

// ---------------- K1: tile-prefix + key base (ROUND-4 VERSION) ----------------
__global__ void k_scan(){
    __shared__ int stot[NKEY];
    __shared__ int sc[1024];
    int n = blockIdx.x; int k = threadIdx.x;
    if (k < NKEY){
        int run = 0;
        #pragma unroll 4
        for (int tl = 0; tl < NTILE; tl++){
            int v = g_tileHist[n][tl][k];
            g_tileHist[n][tl][k] = run;
            run += v;
        }
        stot[k] = run;
    }
    __syncthreads();
    int v0 = (k < NKEY) ? stot[k] : 0;
    sc[k] = v0;
    __syncthreads();
    #pragma unroll
    for (int off = 1; off < 1024; off <<= 1){
        int add = (k >= off) ? sc[k-off] : 0;
        __syncthreads();
        sc[k] += add;
        __syncthreads();
    }
    if (k < NKEY) g_keyBase[n][k] = sc[k] - v0;
}

// ---------------- K2: stable scatter (ROUND-4 VERSION) ----------------
__global__ void k_scatter(){
    __shared__ int skey[TILE];
    int b = blockIdx.x; int n = b >> 7, tl = b & 127;
    int t = threadIdx.x;
    int key = g_codes[n][tl*TILE + t];
    skey[t] = key;
    __syncthreads();
    int r = 0;
    for (int u = 0; u < TILE; u++){
        int ku = skey[u];
        if (u < t && ku == key) r++;
    }
    int pos = g_keyBase[n][key] + g_tileHist[n][tl][key] + r;
    g_perm[n][pos] = tl*TILE + t;
}

// ---------------- K3: chunked attention (ROUND-5 VERSION, measured 117us) ----------------
#define AT_SQ 0
#define AT_SK 1536
#define AT_SVT 3072
#define AT_SM2 (3072+4352)
#define AT_SJ  (3072+4352+128)
#define SMEM_ATTN ((AT_SJ+128)*4)

__global__ void __launch_bounds__(128,4) k_attn(){
    extern __shared__ uint32 smw[];
    uint32* sQ = smw + AT_SQ;
    uint32* sK = smw + AT_SK;
    uint32* sVT32 = smw + AT_SVT;                       // [64][68] words
    unsigned short* sVT = (unsigned short*)sVT32;       // [64][136] uint16
    float* sM2 = (float*)(smw + AT_SM2);
    int*   sJ  = (int*)(smw + AT_SJ);

    int cid = blockIdx.x;
    int n = cid >> 9, rem = cid & 511;
    int g = rem >> 7, k = rem & 127;
    int tid = threadIdx.x;
    int lane = tid & 31, w = tid >> 5;
    int g4 = lane >> 2, t4 = lane & 3;
    int rbase = w*32;

    uint32 qf[2][4];
    float m2lo[2], m2hi[2];
    float o[2][8][4];
    #pragma unroll
    for (int rt = 0; rt < 2; rt++)
        #pragma unroll
        for (int ct = 0; ct < 8; ct++)
            #pragma unroll
            for (int u = 0; u < 4; u++) o[rt][ct][u] = 0.f;
    float rs0[2] = {0.f, 0.f}, rs1[2] = {0.f, 0.f};

    #pragma unroll
    for (int pass = 0; pass < 3; pass++){
        int kc = (pass == 0) ? k : (pass == 1) ? ((k + 127) & 127) : ((k + 1) & 127);
        __syncthreads();
        {
            int p = (g << 14) + (kc << 7) + tid;
            int j = g_perm[n][p];
            int l = j & (LSEQ - 1);
            float inv = g_invn[n][l];
            const float4* xp = (const float4*)&g_xembed[n][l][0];
            float4 a = xp[0], bb = xp[1], c = xp[2], d = xp[3];
            uint32* kr = &sK[tid*12];
            kr[0] = pkbf(a.x*inv, a.y*inv);  kr[1] = pkbf(a.z*inv, a.w*inv);
            kr[2] = pkbf(bb.x*inv, bb.y*inv); kr[3] = pkbf(bb.z*inv, bb.w*inv);
            kr[4] = pkbf(c.x*inv, c.y*inv);  kr[5] = pkbf(c.z*inv, c.w*inv);
            kr[6] = pkbf(d.x*inv, d.y*inv);  kr[7] = pkbf(d.z*inv, d.w*inv);
            if (pass == 0){
                sJ[tid] = j;
                sM2[tid] = g_xnorm[n][l] * LOG2E;
                uint32* qr = &sQ[tid*12];
                qr[0] = pkbf(a.x*LOG2E, a.y*LOG2E);  qr[1] = pkbf(a.z*LOG2E, a.w*LOG2E);
                qr[2] = pkbf(bb.x*LOG2E, bb.y*LOG2E); qr[3] = pkbf(bb.z*LOG2E, bb.w*LOG2E);
                qr[4] = pkbf(c.x*LOG2E, c.y*LOG2E);  qr[5] = pkbf(c.z*LOG2E, c.w*LOG2E);
                qr[6] = pkbf(d.x*LOG2E, d.y*LOG2E);  qr[7] = pkbf(d.z*LOG2E, d.w*LOG2E);
            }
            const float4* vp = (const float4*)&g_yembed[n][l][0];
            #pragma unroll
            for (int t = 0; t < 16; t++){
                float4 v = vp[t];
                sVT[(4*t+0)*136 + tid] = bfr(v.x);
                sVT[(4*t+1)*136 + tid] = bfr(v.y);
                sVT[(4*t+2)*136 + tid] = bfr(v.z);
                sVT[(4*t+3)*136 + tid] = bfr(v.w);
            }
        }
        __syncthreads();
        if (pass == 0){
            #pragma unroll
            for (int rt = 0; rt < 2; rt++){
                int row = rbase + rt*16 + g4;
                qf[rt][0] = sQ[row*12 + t4];
                qf[rt][1] = sQ[(row+8)*12 + t4];
                qf[rt][2] = sQ[row*12 + 4 + t4];
                qf[rt][3] = sQ[(row+8)*12 + 4 + t4];
                m2lo[rt] = sM2[row];
                m2hi[rt] = sM2[row+8];
            }
        }

        for (int nt = 0; nt < 8; nt++){
            uint32 kb[2][2];
            #pragma unroll
            for (int h = 0; h < 2; h++){
                int key = nt*16 + h*8 + g4;
                kb[h][0] = sK[key*12 + t4];
                kb[h][1] = sK[key*12 + 4 + t4];
            }
            float sc2[2][2][4];
            #pragma unroll
            for (int rt = 0; rt < 2; rt++)
                #pragma unroll
                for (int h = 0; h < 2; h++){
                    sc2[rt][h][0] = 0.f; sc2[rt][h][1] = 0.f;
                    sc2[rt][h][2] = 0.f; sc2[rt][h][3] = 0.f;
                    mma16816(sc2[rt][h], qf[rt], kb[h][0], kb[h][1]);
                }
            uint32 pf[2][4];
            #pragma unroll
            for (int rt = 0; rt < 2; rt++){
                #pragma unroll
                for (int h = 0; h < 2; h++){
                    float e0 = ex2a(sc2[rt][h][0] - m2lo[rt]);
                    float e1 = ex2a(sc2[rt][h][1] - m2lo[rt]);
                    float e2 = ex2a(sc2[rt][h][2] - m2hi[rt]);
                    float e3 = ex2a(sc2[rt][h][3] - m2hi[rt]);
                    rs0[rt] += e0 + e1;
                    rs1[rt] += e2 + e3;
                    pf[rt][h*2]   = pkbf(e0, e1);
                    pf[rt][h*2+1] = pkbf(e2, e3);
                }
            }
            #pragma unroll
            for (int ct = 0; ct < 8; ct++){
                int ch = ct*8 + g4;
                uint32 vb0 = sVT32[ch*68 + nt*8 + t4];
                uint32 vb1 = sVT32[ch*68 + nt*8 + 4 + t4];
                mma16816(o[0][ct], pf[0], vb0, vb1);
                mma16816(o[1][ct], pf[1], vb0, vb1);
            }
        }
    }

    // ---- epilogue ----
    #pragma unroll
    for (int rt = 0; rt < 2; rt++){
        float v0 = rs0[rt];
        v0 += __shfl_xor_sync(0xffffffffu, v0, 1);
        v0 += __shfl_xor_sync(0xffffffffu, v0, 2);
        float v1 = rs1[rt];
        v1 += __shfl_xor_sync(0xffffffffu, v1, 1);
        v1 += __shfl_xor_sync(0xffffffffu, v1, 2);
        float i0 = 1.f / v0, i1 = 1.f / v1;
        int row0 = rbase + rt*16 + g4, row1 = row0 + 8;
        int j0 = sJ[row0], j1 = sJ[row1];
        if (t4 == 0){
            g_bs[n][j0] = (sM2[row0] + lg2a(v0)) * LN2;
            g_bs[n][j1] = (sM2[row1] + lg2a(v1)) * LN2;
        }
        unsigned short* r0p = &g_ret[n][j0][0];
        unsigned short* r1p = &g_ret[n][j1][0];
        #pragma unroll
        for (int ct = 0; ct < 8; ct++){
            int ch = ct*8 + 2*t4;
            *(uint32*)&r0p[ch] = pkbf(o[rt][ct][0]*i0, o[rt][ct][1]*i0);
            *(uint32*)&r1p[ch] = pkbf(o[rt][ct][2]*i1, o[rt][ct][3]*i1);
        }
    }
}

// ---------------- K4: combine + residual + hist re-zero ----------------
__global__ void k_combine(const float* __restrict__ x, float* __restrict__ out){
    int gt = blockIdx.x * 256 + threadIdx.x;
    int n = gt >> 14, l = gt & (LSEQ - 1);
    float b0 = g_bs[n][l];
    float b1 = g_bs[n][LSEQ + l];
    float b2 = g_bs[n][2*LSEQ + l];
    float b3 = g_bs[n][3*LSEQ + l];
    float mx = fmaxf(fmaxf(b0, b1), fmaxf(b2, b3));
    float e0 = ex2a((b0 - mx)*LOG2E), e1 = ex2a((b1 - mx)*LOG2E);
    float e2 = ex2a((b2 - mx)*LOG2E), e3 = ex2a((b3 - mx)*LOG2E);
    float inv = 1.f / (e0 + e1 + e2 + e3);
    float p0 = e0*inv, p1 = e1*inv, p2 = e2*inv, p3 = e3*inv;

    const uint4* r0 = (const uint4*)&g_ret[n][l][0];
    const uint4* r1 = (const uint4*)&g_ret[n][LSEQ + l][0];
    const uint4* r2 = (const uint4*)&g_ret[n][2*LSEQ + l][0];
    const uint4* r3 = (const uint4*)&g_ret[n][3*LSEQ + l][0];
    const float4* x4 = (const float4*)&x[((size_t)n*LSEQ + l)*64];
    float4* o4 = (float4*)&out[((size_t)n*LSEQ + l)*64];
    #pragma unroll
    for (int t = 0; t < 8; t++){
        uint4 u0 = r0[t], u1 = r1[t], u2 = r2[t], u3 = r3[t];
        float4 xa = x4[2*t], xb = x4[2*t+1];
        float4 oa, ob;
        oa.x = xa.x + p0*blo(u0.x) + p1*blo(u1.x) + p2*blo(u2.x) + p3*blo(u3.x);
        oa.y = xa.y + p0*bhi(u0.x) + p1*bhi(u1.x) + p2*bhi(u2.x) + p3*bhi(u3.x);
        oa.z = xa.z + p0*blo(u0.y) + p1*blo(u1.y) + p2*blo(u2.y) + p3*blo(u3.y);
        oa.w = xa.w + p0*bhi(u0.y) + p1*bhi(u1.y) + p2*bhi(u2.y) + p3*bhi(u3.y);
        ob.x = xb.x + p0*blo(u0.z) + p1*blo(u1.z) + p2*blo(u2.z) + p3*blo(u3.z);
        ob.y = xb.y + p0*bhi(u0.z) + p1*bhi(u1.z) + p2*bhi(u2.z) + p3*bhi(u3.z);
        ob.z = xb.z + p0*blo(u0.w) + p1*blo(u1.w) + p2*blo(u2.w) + p3*blo(u3.w);
        ob.w = xb.w + p0*bhi(u0.w) + p1*bhi(u1.w) + p2*bhi(u2.w) + p3*bhi(u3.w);
        o4[2*t] = oa;
        o4[2*t+1] = ob;
    }
    int* hist = &g_tileHist[0][0][0];
    const int tot = NB*NTILE*NKEY;
    for (int idx = gt; idx < tot; idx += NB*LSEQ) hist[idx] = 0;
}

// ---------------- launch ----------------
extern "C" void kernel_launch(void* const* d_in, const int* in_sizes, int n_in,
                              void* d_out, int out_size){
    const float* x  = (const float*)d_in[0];
    const float* wm = (const float*)d_in[1];
    const float* wa = (const float*)d_in[2];
    const float* wb = (const float*)d_in[3];
    const float* rt = (const float*)d_in[4];
    float* out = (float*)d_out;

    static bool attr_done = false;
    if (!attr_done){
        cudaFuncSetAttribute(k_ehh, cudaFuncAttributeMaxDynamicSharedMemorySize, SMEM_EHH);
        attr_done = true;
    }

    k_ehh    <<<NB*(LSEQ/TL), 256, SMEM_EHH>>>(x, wm, wa, wb, rt);
    k_scan   <<<NB, 1024>>>();
    k_scatter<<<NB*NTILE, TILE>>>();
    k_attn   <<<NB*NH*KCH, 128, SMEM_ATTN>>>();
    k_combine<<<(NB*LSEQ)/256, 256>>>(x, out);
}

// round 8
// speedup vs baseline: 2.9320x; 1.2365x over previous
#include <cuda_runtime.h>
#include <cstdint>

#define NB 4
#define LSEQ 16384
#define CCH 64
#define CM 16
#define NH 4
#define HB 128
#define KCH 128
#define JTOT (NH*LSEQ)
#define NKEY 640
#define TILE 512
#define NTILE (JTOT/TILE)   // 128
#define TL2 128

typedef unsigned long long ull;
typedef unsigned int uint32;

// ---------------- device scratch ----------------
__device__ __align__(16) float g_xembed[NB][LSEQ][CM];
__device__ __align__(16) float g_yembed[NB][LSEQ][CCH];
__device__ float g_xnorm[NB][LSEQ];
__device__ float g_invn[NB][LSEQ];
__device__ int   g_codes[NB][JTOT];
__device__ int   g_perm[NB][JTOT];
__device__ int   g_tileHist[NB][NTILE][NKEY];   // zeroed at load; re-zeroed by k_combine
__device__ int   g_keyBase[NB][NKEY];
__device__ __align__(16) unsigned short g_ret[NB][JTOT][CCH];   // bf16
__device__ float g_bs[NB][JTOT];

// ---------------- helpers ----------------
__device__ __forceinline__ float ex2a(float t){
    float r; asm("ex2.approx.f32 %0,%1;" : "=f"(r) : "f"(t)); return r;
}
__device__ __forceinline__ float lg2a(float t){
    float r; asm("lg2.approx.f32 %0,%1;" : "=f"(r) : "f"(t)); return r;
}
__device__ __forceinline__ uint32 pkbf(float lo, float hi){
    uint32 r; asm("cvt.rn.bf16x2.f32 %0, %1, %2;" : "=r"(r) : "f"(hi), "f"(lo)); return r;
}
__device__ __forceinline__ unsigned short bfr(float x){
    unsigned short r; asm("cvt.rn.bf16.f32 %0,%1;" : "=h"(r) : "f"(x)); return r;
}
__device__ __forceinline__ float blo(uint32 u){ return __uint_as_float(u << 16); }
__device__ __forceinline__ float bhi(uint32 u){ return __uint_as_float(u & 0xffff0000u); }

__device__ __forceinline__ void mma16816(float* d, const uint32* a, uint32 b0, uint32 b1){
    asm volatile("mma.sync.aligned.m16n8k16.row.col.f32.bf16.bf16.f32 "
        "{%0,%1,%2,%3},{%4,%5,%6,%7},{%8,%9},{%0,%1,%2,%3};"
        : "+f"(d[0]), "+f"(d[1]), "+f"(d[2]), "+f"(d[3])
        : "r"(a[0]), "r"(a[1]), "r"(a[2]), "r"(a[3]), "r"(b0), "r"(b1));
}

#define LOG2E 1.4426950408889634f
#define LN2   0.6931471805599453f

// ---------------- K0: fused embed + hash + hist (register-blocked v2) ----------------
// smem layout (floats) — ALL region offsets multiples of 4 floats (16B) for float4 access:
//   sx  [130][65]  = 8450 (padded to 8452)
//   swm [192][16]  = 3072
//   swa [64][64]   = 4096
//   swb [64]       = 64
//   sR  [512][16]  = 8192
//   sxe [128][20]  = 2560
#define E2_SX   0
#define E2_SWM  8452
#define E2_SWA  (8452+3072)
#define E2_SWB  (8452+3072+4096)
#define E2_SR   (8452+3072+4096+64)
#define E2_SXE  (8452+3072+4096+64+8192)
#define E2_TOT  (E2_SXE+2560)
#define SMEM_EHH (E2_TOT*4)

__global__ void __launch_bounds__(256) k_ehh(
        const float* __restrict__ x, const float* __restrict__ wm,
        const float* __restrict__ wa, const float* __restrict__ wb,
        const float* __restrict__ rot){
    extern __shared__ float sm[];
    float* sx  = sm + E2_SX;    // [130][65]
    float* swm = sm + E2_SWM;   // [(c*3+tap)*16 + f]
    float* swa = sm + E2_SWA;   // [c*64 + o]
    float* swb = sm + E2_SWB;
    float* sR  = sm + E2_SR;    // [(h*128+i)*16 + f]
    float* sxe = sm + E2_SXE;   // [row*20 + f]

    int b = blockIdx.x;
    int n = b / (LSEQ/TL2);
    int l0 = (b % (LSEQ/TL2)) * TL2;
    int tid = threadIdx.x;

    // ---- stage ----
    for (int idx = tid; idx < 130*64; idx += 256){
        int r = idx >> 6, c = idx & 63;
        int l = l0 + r - 1;
        sx[r*65 + c] = (l >= 0 && l < LSEQ) ? x[((size_t)n*LSEQ + l)*64 + c] : 0.f;
    }
    for (int idx = tid; idx < 3072; idx += 256){
        int f = idx / 192, rem = idx % 192;
        swm[rem*16 + f] = wm[idx];
    }
    for (int idx = tid; idx < 4096; idx += 256){
        int o = idx >> 6, c = idx & 63;
        swa[c*64 + o] = wa[idx];
    }
    if (tid < 64) swb[tid] = wb[tid];
    for (int idx = tid; idx < 8192; idx += 256){
        int f = idx >> 9, hi = idx & 511;
        sR[hi*16 + f] = rot[idx];
    }
    __syncthreads();

    // ---- x_embed: thread -> (rowx in [0,64), fg in [0,4)); 2 row-blocks ----
    {
        int rowx = tid >> 2, fg = (tid & 3) * 4;
        float a0[2][4];
        #pragma unroll
        for (int rb = 0; rb < 2; rb++)
            #pragma unroll
            for (int u = 0; u < 4; u++) a0[rb][u] = 0.f;
        #pragma unroll 4
        for (int c = 0; c < 64; c++){
            float4 w0 = *(const float4*)&swm[(c*3+0)*16 + fg];
            float4 w1 = *(const float4*)&swm[(c*3+1)*16 + fg];
            float4 w2 = *(const float4*)&swm[(c*3+2)*16 + fg];
            #pragma unroll
            for (int rb = 0; rb < 2; rb++){
                int r = rowx + rb*64;      // sx row r..r+2 = l0+r-1 .. l0+r+1
                float x0 = sx[(r    )*65 + c];
                float x1 = sx[(r + 1)*65 + c];
                float x2 = sx[(r + 2)*65 + c];
                a0[rb][0] = fmaf(x0, w0.x, fmaf(x1, w1.x, fmaf(x2, w2.x, a0[rb][0])));
                a0[rb][1] = fmaf(x0, w0.y, fmaf(x1, w1.y, fmaf(x2, w2.y, a0[rb][1])));
                a0[rb][2] = fmaf(x0, w0.z, fmaf(x1, w1.z, fmaf(x2, w2.z, a0[rb][2])));
                a0[rb][3] = fmaf(x0, w0.w, fmaf(x1, w1.w, fmaf(x2, w2.w, a0[rb][3])));
            }
        }
        #pragma unroll
        for (int rb = 0; rb < 2; rb++){
            int r = rowx + rb*64;
            float4 v; v.x = a0[rb][0]; v.y = a0[rb][1]; v.z = a0[rb][2]; v.w = a0[rb][3];
            *(float4*)&g_xembed[n][l0 + r][fg] = v;
            *(float4*)&sxe[r*20 + fg] = v;
        }
    }

    // ---- y_embed: thread -> (rowy in [0,32), og in [0,8)); 4 row-blocks ----
    {
        int rowy = tid >> 3, ob = (tid & 7) * 8;
        float4 acc0[4], acc1[4];
        float4 bias0 = *(const float4*)&swb[ob];
        float4 bias1 = *(const float4*)&swb[ob + 4];
        #pragma unroll
        for (int blk = 0; blk < 4; blk++){ acc0[blk] = bias0; acc1[blk] = bias1; }
        #pragma unroll 4
        for (int c = 0; c < 64; c++){
            float4 w0 = *(const float4*)&swa[c*64 + ob];
            float4 w1 = *(const float4*)&swa[c*64 + ob + 4];
            #pragma unroll
            for (int blk = 0; blk < 4; blk++){
                float xv = sx[(rowy + blk*32 + 1)*65 + c];
                acc0[blk].x = fmaf(xv, w0.x, acc0[blk].x);
                acc0[blk].y = fmaf(xv, w0.y, acc0[blk].y);
                acc0[blk].z = fmaf(xv, w0.z, acc0[blk].z);
                acc0[blk].w = fmaf(xv, w0.w, acc0[blk].w);
                acc1[blk].x = fmaf(xv, w1.x, acc1[blk].x);
                acc1[blk].y = fmaf(xv, w1.y, acc1[blk].y);
                acc1[blk].z = fmaf(xv, w1.z, acc1[blk].z);
                acc1[blk].w = fmaf(xv, w1.w, acc1[blk].w);
            }
        }
        #pragma unroll
        for (int blk = 0; blk < 4; blk++){
            int r = rowy + blk*32;
            *(float4*)&g_yembed[n][l0 + r][ob]     = acc0[blk];
            *(float4*)&g_yembed[n][l0 + r][ob + 4] = acc1[blk];
        }
    }
    __syncthreads();

    // ---- hash: thread -> (h = tid>>6, rowbase = tid&63); 2 rows ----
    {
        int h = tid >> 6, rowbase = tid & 63;
        const float* Rh = &sR[(h*128)*16];
        #pragma unroll
        for (int rb = 0; rb < 2; rb++){
            int r = rowbase + rb*64;
            int l = l0 + r;
            float4 q0 = *(const float4*)&sxe[r*20 + 0];
            float4 q1 = *(const float4*)&sxe[r*20 + 4];
            float4 q2 = *(const float4*)&sxe[r*20 + 8];
            float4 q3 = *(const float4*)&sxe[r*20 + 12];
            if (h == 0){
                float nn = q0.x*q0.x + q0.y*q0.y + q0.z*q0.z + q0.w*q0.w;
                nn += q1.x*q1.x + q1.y*q1.y + q1.z*q1.z + q1.w*q1.w;
                nn += q2.x*q2.x + q2.y*q2.y + q2.z*q2.z + q2.w*q2.w;
                nn += q3.x*q3.x + q3.y*q3.y + q3.z*q3.z + q3.w*q3.w;
                nn = sqrtf(nn);
                g_xnorm[n][l] = nn;
                g_invn[n][l]  = 1.f / fmaxf(nn, 5e-5f);
            }
            float m1 = -1e30f, m2 = 1e30f; int i1 = 0, i2 = 0;
            #pragma unroll 2
            for (int i = 0; i < 128; i++){
                float4 r0 = *(const float4*)&Rh[i*16 + 0];
                float4 r1 = *(const float4*)&Rh[i*16 + 4];
                float4 r2 = *(const float4*)&Rh[i*16 + 8];
                float4 r3 = *(const float4*)&Rh[i*16 + 12];
                float v = q0.x*r0.x + q0.y*r0.y + q0.z*r0.z + q0.w*r0.w;
                v += q1.x*r1.x + q1.y*r1.y + q1.z*r1.z + q1.w*r1.w;
                v += q2.x*r2.x + q2.y*r2.y + q2.z*r2.z + q2.w*r2.w;
                v += q3.x*r3.x + q3.y*r3.y + q3.z*r3.z + q3.w*r3.w;
                if (v > m1){ m1 = v; i1 = i; }
                if (v < m2){ m2 = v; i2 = i; }
            }
            int code = ((m1 >= -m2) ? i1 : (HB + i2)) + h*HB;
            int j = h*LSEQ + l;
            g_codes[n][j] = code;
            atomicAdd(&g_tileHist[n][j >> 9][code], 1);
        }
    }
}

// ---------------- K1: tile-prefix + key base (UNCHANGED) ----------------
__global__ void k_scan(){
    __shared__ int stot[NKEY];
    __shared__ int sc[1024];
    int n = blockIdx.x; int k = threadIdx.x;
    if (k < NKEY){
        int run = 0;
        #pragma unroll 4
        for (int tl = 0; tl < NTILE; tl++){
            int v = g_tileHist[n][tl][k];
            g_tileHist[n][tl][k] = run;
            run += v;
        }
        stot[k] = run;
    }
    __syncthreads();
    int v0 = (k < NKEY) ? stot[k] : 0;
    sc[k] = v0;
    __syncthreads();
    #pragma unroll
    for (int off = 1; off < 1024; off <<= 1){
        int add = (k >= off) ? sc[k-off] : 0;
        __syncthreads();
        sc[k] += add;
        __syncthreads();
    }
    if (k < NKEY) g_keyBase[n][k] = sc[k] - v0;
}

// ---------------- K2: stable scatter (UNCHANGED) ----------------
__global__ void k_scatter(){
    __shared__ int skey[TILE];
    int b = blockIdx.x; int n = b >> 7, tl = b & 127;
    int t = threadIdx.x;
    int key = g_codes[n][tl*TILE + t];
    skey[t] = key;
    __syncthreads();
    int r = 0;
    for (int u = 0; u < TILE; u++){
        int ku = skey[u];
        if (u < t && ku == key) r++;
    }
    int pos = g_keyBase[n][key] + g_tileHist[n][tl][key] + r;
    g_perm[n][pos] = tl*TILE + t;
}

// ---------------- K3: chunked attention (UNCHANGED, measured 117us) ----------------
#define AT_SQ 0
#define AT_SK 1536
#define AT_SVT 3072
#define AT_SM2 (3072+4352)
#define AT_SJ  (3072+4352+128)
#define SMEM_ATTN ((AT_SJ+128)*4)

__global__ void __launch_bounds__(128,4) k_attn(){
    extern __shared__ uint32 smw[];
    uint32* sQ = smw + AT_SQ;
    uint32* sK = smw + AT_SK;
    uint32* sVT32 = smw + AT_SVT;                       // [64][68] words
    unsigned short* sVT = (unsigned short*)sVT32;       // [64][136] uint16
    float* sM2 = (float*)(smw + AT_SM2);
    int*   sJ  = (int*)(smw + AT_SJ);

    int cid = blockIdx.x;
    int n = cid >> 9, rem = cid & 511;
    int g = rem >> 7, k = rem & 127;
    int tid = threadIdx.x;
    int lane = tid & 31, w = tid >> 5;
    int g4 = lane >> 2, t4 = lane & 3;
    int rbase = w*32;

    uint32 qf[2][4];
    float m2lo[2], m2hi[2];
    float o[2][8][4];
    #pragma unroll
    for (int rt = 0; rt < 2; rt++)
        #pragma unroll
        for (int ct = 0; ct < 8; ct++)
            #pragma unroll
            for (int u = 0; u < 4; u++) o[rt][ct][u] = 0.f;
    float rs0[2] = {0.f, 0.f}, rs1[2] = {0.f, 0.f};

    #pragma unroll
    for (int pass = 0; pass < 3; pass++){
        int kc = (pass == 0) ? k : (pass == 1) ? ((k + 127) & 127) : ((k + 1) & 127);
        __syncthreads();
        {
            int p = (g << 14) + (kc << 7) + tid;
            int j = g_perm[n][p];
            int l = j & (LSEQ - 1);
            float inv = g_invn[n][l];
            const float4* xp = (const float4*)&g_xembed[n][l][0];
            float4 a = xp[0], bb = xp[1], c = xp[2], d = xp[3];
            uint32* kr = &sK[tid*12];
            kr[0] = pkbf(a.x*inv, a.y*inv);  kr[1] = pkbf(a.z*inv, a.w*inv);
            kr[2] = pkbf(bb.x*inv, bb.y*inv); kr[3] = pkbf(bb.z*inv, bb.w*inv);
            kr[4] = pkbf(c.x*inv, c.y*inv);  kr[5] = pkbf(c.z*inv, c.w*inv);
            kr[6] = pkbf(d.x*inv, d.y*inv);  kr[7] = pkbf(d.z*inv, d.w*inv);
            if (pass == 0){
                sJ[tid] = j;
                sM2[tid] = g_xnorm[n][l] * LOG2E;
                uint32* qr = &sQ[tid*12];
                qr[0] = pkbf(a.x*LOG2E, a.y*LOG2E);  qr[1] = pkbf(a.z*LOG2E, a.w*LOG2E);
                qr[2] = pkbf(bb.x*LOG2E, bb.y*LOG2E); qr[3] = pkbf(bb.z*LOG2E, bb.w*LOG2E);
                qr[4] = pkbf(c.x*LOG2E, c.y*LOG2E);  qr[5] = pkbf(c.z*LOG2E, c.w*LOG2E);
                qr[6] = pkbf(d.x*LOG2E, d.y*LOG2E);  qr[7] = pkbf(d.z*LOG2E, d.w*LOG2E);
            }
            const float4* vp = (const float4*)&g_yembed[n][l][0];
            #pragma unroll
            for (int t = 0; t < 16; t++){
                float4 v = vp[t];
                sVT[(4*t+0)*136 + tid] = bfr(v.x);
                sVT[(4*t+1)*136 + tid] = bfr(v.y);
                sVT[(4*t+2)*136 + tid] = bfr(v.z);
                sVT[(4*t+3)*136 + tid] = bfr(v.w);
            }
        }
        __syncthreads();
        if (pass == 0){
            #pragma unroll
            for (int rt = 0; rt < 2; rt++){
                int row = rbase + rt*16 + g4;
                qf[rt][0] = sQ[row*12 + t4];
                qf[rt][1] = sQ[(row+8)*12 + t4];
                qf[rt][2] = sQ[row*12 + 4 + t4];
                qf[rt][3] = sQ[(row+8)*12 + 4 + t4];
                m2lo[rt] = sM2[row];
                m2hi[rt] = sM2[row+8];
            }
        }

        for (int nt = 0; nt < 8; nt++){
            uint32 kb[2][2];
            #pragma unroll
            for (int h = 0; h < 2; h++){
                int key = nt*16 + h*8 + g4;
                kb[h][0] = sK[key*12 + t4];
                kb[h][1] = sK[key*12 + 4 + t4];
            }
            float sc2[2][2][4];
            #pragma unroll
            for (int rt = 0; rt < 2; rt++)
                #pragma unroll
                for (int h = 0; h < 2; h++){
                    sc2[rt][h][0] = 0.f; sc2[rt][h][1] = 0.f;
                    sc2[rt][h][2] = 0.f; sc2[rt][h][3] = 0.f;
                    mma16816(sc2[rt][h], qf[rt], kb[h][0], kb[h][1]);
                }
            uint32 pf[2][4];
            #pragma unroll
            for (int rt = 0; rt < 2; rt++){
                #pragma unroll
                for (int h = 0; h < 2; h++){
                    float e0 = ex2a(sc2[rt][h][0] - m2lo[rt]);
                    float e1 = ex2a(sc2[rt][h][1] - m2lo[rt]);
                    float e2 = ex2a(sc2[rt][h][2] - m2hi[rt]);
                    float e3 = ex2a(sc2[rt][h][3] - m2hi[rt]);
                    rs0[rt] += e0 + e1;
                    rs1[rt] += e2 + e3;
                    pf[rt][h*2]   = pkbf(e0, e1);
                    pf[rt][h*2+1] = pkbf(e2, e3);
                }
            }
            #pragma unroll
            for (int ct = 0; ct < 8; ct++){
                int ch = ct*8 + g4;
                uint32 vb0 = sVT32[ch*68 + nt*8 + t4];
                uint32 vb1 = sVT32[ch*68 + nt*8 + 4 + t4];
                mma16816(o[0][ct], pf[0], vb0, vb1);
                mma16816(o[1][ct], pf[1], vb0, vb1);
            }
        }
    }

    // ---- epilogue ----
    #pragma unroll
    for (int rt = 0; rt < 2; rt++){
        float v0 = rs0[rt];
        v0 += __shfl_xor_sync(0xffffffffu, v0, 1);
        v0 += __shfl_xor_sync(0xffffffffu, v0, 2);
        float v1 = rs1[rt];
        v1 += __shfl_xor_sync(0xffffffffu, v1, 1);
        v1 += __shfl_xor_sync(0xffffffffu, v1, 2);
        float i0 = 1.f / v0, i1 = 1.f / v1;
        int row0 = rbase + rt*16 + g4, row1 = row0 + 8;
        int j0 = sJ[row0], j1 = sJ[row1];
        if (t4 == 0){
            g_bs[n][j0] = (sM2[row0] + lg2a(v0)) * LN2;
            g_bs[n][j1] = (sM2[row1] + lg2a(v1)) * LN2;
        }
        unsigned short* r0p = &g_ret[n][j0][0];
        unsigned short* r1p = &g_ret[n][j1][0];
        #pragma unroll
        for (int ct = 0; ct < 8; ct++){
            int ch = ct*8 + 2*t4;
            *(uint32*)&r0p[ch] = pkbf(o[rt][ct][0]*i0, o[rt][ct][1]*i0);
            *(uint32*)&r1p[ch] = pkbf(o[rt][ct][2]*i1, o[rt][ct][3]*i1);
        }
    }
}

// ---------------- K4: combine + residual + hist re-zero (UNCHANGED) ----------------
__global__ void k_combine(const float* __restrict__ x, float* __restrict__ out){
    int gt = blockIdx.x * 256 + threadIdx.x;
    int n = gt >> 14, l = gt & (LSEQ - 1);
    float b0 = g_bs[n][l];
    float b1 = g_bs[n][LSEQ + l];
    float b2 = g_bs[n][2*LSEQ + l];
    float b3 = g_bs[n][3*LSEQ + l];
    float mx = fmaxf(fmaxf(b0, b1), fmaxf(b2, b3));
    float e0 = ex2a((b0 - mx)*LOG2E), e1 = ex2a((b1 - mx)*LOG2E);
    float e2 = ex2a((b2 - mx)*LOG2E), e3 = ex2a((b3 - mx)*LOG2E);
    float inv = 1.f / (e0 + e1 + e2 + e3);
    float p0 = e0*inv, p1 = e1*inv, p2 = e2*inv, p3 = e3*inv;

    const uint4* r0 = (const uint4*)&g_ret[n][l][0];
    const uint4* r1 = (const uint4*)&g_ret[n][LSEQ + l][0];
    const uint4* r2 = (const uint4*)&g_ret[n][2*LSEQ + l][0];
    const uint4* r3 = (const uint4*)&g_ret[n][3*LSEQ + l][0];
    const float4* x4 = (const float4*)&x[((size_t)n*LSEQ + l)*64];
    float4* o4 = (float4*)&out[((size_t)n*LSEQ + l)*64];
    #pragma unroll
    for (int t = 0; t < 8; t++){
        uint4 u0 = r0[t], u1 = r1[t], u2 = r2[t], u3 = r3[t];
        float4 xa = x4[2*t], xb = x4[2*t+1];
        float4 oa, ob;
        oa.x = xa.x + p0*blo(u0.x) + p1*blo(u1.x) + p2*blo(u2.x) + p3*blo(u3.x);
        oa.y = xa.y + p0*bhi(u0.x) + p1*bhi(u1.x) + p2*bhi(u2.x) + p3*bhi(u3.x);
        oa.z = xa.z + p0*blo(u0.y) + p1*blo(u1.y) + p2*blo(u2.y) + p3*blo(u3.y);
        oa.w = xa.w + p0*bhi(u0.y) + p1*bhi(u1.y) + p2*bhi(u2.y) + p3*bhi(u3.y);
        ob.x = xb.x + p0*blo(u0.z) + p1*blo(u1.z) + p2*blo(u2.z) + p3*blo(u3.z);
        ob.y = xb.y + p0*bhi(u0.z) + p1*bhi(u1.z) + p2*bhi(u2.z) + p3*bhi(u3.z);
        ob.z = xb.z + p0*blo(u0.w) + p1*blo(u1.w) + p2*blo(u2.w) + p3*blo(u3.w);
        ob.w = xb.w + p0*bhi(u0.w) + p1*bhi(u1.w) + p2*bhi(u2.w) + p3*bhi(u3.w);
        o4[2*t] = oa;
        o4[2*t+1] = ob;
    }
    int* hist = &g_tileHist[0][0][0];
    const int tot = NB*NTILE*NKEY;
    for (int idx = gt; idx < tot; idx += NB*LSEQ) hist[idx] = 0;
}

// ---------------- launch ----------------
extern "C" void kernel_launch(void* const* d_in, const int* in_sizes, int n_in,
                              void* d_out, int out_size){
    const float* x  = (const float*)d_in[0];
    const float* wm = (const float*)d_in[1];
    const float* wa = (const float*)d_in[2];
    const float* wb = (const float*)d_in[3];
    const float* rt = (const float*)d_in[4];
    float* out = (float*)d_out;

    static bool attr_done = false;
    if (!attr_done){
        cudaFuncSetAttribute(k_ehh, cudaFuncAttributeMaxDynamicSharedMemorySize, SMEM_EHH);
        attr_done = true;
    }

    k_ehh    <<<NB*(LSEQ/TL2), 256, SMEM_EHH>>>(x, wm, wa, wb, rt);
    k_scan   <<<NB, 1024>>>();
    k_scatter<<<NB*NTILE, TILE>>>();
    k_attn   <<<NB*NH*KCH, 128, SMEM_ATTN>>>();
    k_combine<<<(NB*LSEQ)/256, 256>>>(x, out);
}

// round 9
// speedup vs baseline: 3.2144x; 1.0963x over previous
#include <cuda_runtime.h>
#include <cstdint>

#define NB 4
#define LSEQ 16384
#define CCH 64
#define CM 16
#define NH 4
#define HB 128
#define KCH 128
#define JTOT (NH*LSEQ)
#define NKEY 640
#define TILE 512
#define NTILE (JTOT/TILE)   // 128
#define TL2 128

typedef unsigned long long ull;
typedef unsigned int uint32;

// ---------------- device scratch ----------------
__device__ __align__(16) unsigned short g_xbf[NB][LSEQ][CM];   // normalized x_embed, bf16 (32B/row)
__device__ __align__(16) unsigned short g_ybf[NB][LSEQ][CCH];  // y_embed, bf16 (128B/row)
__device__ float g_xnorm[NB][LSEQ];
__device__ int   g_codes[NB][JTOT];
__device__ int   g_perm[NB][JTOT];
__device__ int   g_tileHist[NB][NTILE][NKEY];   // zeroed at load; re-zeroed by k_combine
__device__ int   g_keyBase[NB][NKEY];
__device__ __align__(16) unsigned short g_ret[NB][JTOT][CCH];   // bf16
__device__ float g_bs[NB][JTOT];

// ---------------- helpers ----------------
__device__ __forceinline__ float ex2a(float t){
    float r; asm("ex2.approx.f32 %0,%1;" : "=f"(r) : "f"(t)); return r;
}
__device__ __forceinline__ float lg2a(float t){
    float r; asm("lg2.approx.f32 %0,%1;" : "=f"(r) : "f"(t)); return r;
}
__device__ __forceinline__ uint32 pkbf(float lo, float hi){
    uint32 r; asm("cvt.rn.bf16x2.f32 %0, %1, %2;" : "=r"(r) : "f"(hi), "f"(lo)); return r;
}
__device__ __forceinline__ float blo(uint32 u){ return __uint_as_float(u << 16); }
__device__ __forceinline__ float bhi(uint32 u){ return __uint_as_float(u & 0xffff0000u); }

__device__ __forceinline__ void mma16816(float* d, const uint32* a, uint32 b0, uint32 b1){
    asm volatile("mma.sync.aligned.m16n8k16.row.col.f32.bf16.bf16.f32 "
        "{%0,%1,%2,%3},{%4,%5,%6,%7},{%8,%9},{%0,%1,%2,%3};"
        : "+f"(d[0]), "+f"(d[1]), "+f"(d[2]), "+f"(d[3])
        : "r"(a[0]), "r"(a[1]), "r"(a[2]), "r"(a[3]), "r"(b0), "r"(b1));
}
__device__ __forceinline__ void ldsm4t(uint32& r0, uint32& r1, uint32& r2, uint32& r3, uint32 saddr){
    asm volatile("ldmatrix.sync.aligned.m8n8.x4.trans.shared.b16 {%0,%1,%2,%3},[%4];"
        : "=r"(r0), "=r"(r1), "=r"(r2), "=r"(r3) : "r"(saddr));
}

#define LOG2E 1.4426950408889634f
#define LN2   0.6931471805599453f

// ---------------- K0: fused embed + hash + hist (bf16 outputs) ----------------
#define E2_SX   0
#define E2_SWM  8452
#define E2_SWA  (8452+3072)
#define E2_SWB  (8452+3072+4096)
#define E2_SR   (8452+3072+4096+64)
#define E2_SXE  (8452+3072+4096+64+8192)
#define E2_TOT  (E2_SXE+2560)
#define SMEM_EHH (E2_TOT*4)

__global__ void __launch_bounds__(256) k_ehh(
        const float* __restrict__ x, const float* __restrict__ wm,
        const float* __restrict__ wa, const float* __restrict__ wb,
        const float* __restrict__ rot){
    extern __shared__ float sm[];
    float* sx  = sm + E2_SX;    // [130][65]
    float* swm = sm + E2_SWM;   // [(c*3+tap)*16 + f]
    float* swa = sm + E2_SWA;   // [c*64 + o]
    float* swb = sm + E2_SWB;
    float* sR  = sm + E2_SR;    // [(h*128+i)*16 + f]
    float* sxe = sm + E2_SXE;   // [row*20 + f]

    int b = blockIdx.x;
    int n = b / (LSEQ/TL2);
    int l0 = (b % (LSEQ/TL2)) * TL2;
    int tid = threadIdx.x;

    for (int idx = tid; idx < 130*64; idx += 256){
        int r = idx >> 6, c = idx & 63;
        int l = l0 + r - 1;
        sx[r*65 + c] = (l >= 0 && l < LSEQ) ? x[((size_t)n*LSEQ + l)*64 + c] : 0.f;
    }
    for (int idx = tid; idx < 3072; idx += 256){
        int f = idx / 192, rem = idx % 192;
        swm[rem*16 + f] = wm[idx];
    }
    for (int idx = tid; idx < 4096; idx += 256){
        int o = idx >> 6, c = idx & 63;
        swa[c*64 + o] = wa[idx];
    }
    if (tid < 64) swb[tid] = wb[tid];
    for (int idx = tid; idx < 8192; idx += 256){
        int f = idx >> 9, hi = idx & 511;
        sR[hi*16 + f] = rot[idx];
    }
    __syncthreads();

    // x_embed -> smem only
    {
        int rowx = tid >> 2, fg = (tid & 3) * 4;
        float a0[2][4];
        #pragma unroll
        for (int rb = 0; rb < 2; rb++)
            #pragma unroll
            for (int u = 0; u < 4; u++) a0[rb][u] = 0.f;
        #pragma unroll 4
        for (int c = 0; c < 64; c++){
            float4 w0 = *(const float4*)&swm[(c*3+0)*16 + fg];
            float4 w1 = *(const float4*)&swm[(c*3+1)*16 + fg];
            float4 w2 = *(const float4*)&swm[(c*3+2)*16 + fg];
            #pragma unroll
            for (int rb = 0; rb < 2; rb++){
                int r = rowx + rb*64;
                float x0 = sx[(r    )*65 + c];
                float x1 = sx[(r + 1)*65 + c];
                float x2 = sx[(r + 2)*65 + c];
                a0[rb][0] = fmaf(x0, w0.x, fmaf(x1, w1.x, fmaf(x2, w2.x, a0[rb][0])));
                a0[rb][1] = fmaf(x0, w0.y, fmaf(x1, w1.y, fmaf(x2, w2.y, a0[rb][1])));
                a0[rb][2] = fmaf(x0, w0.z, fmaf(x1, w1.z, fmaf(x2, w2.z, a0[rb][2])));
                a0[rb][3] = fmaf(x0, w0.w, fmaf(x1, w1.w, fmaf(x2, w2.w, a0[rb][3])));
            }
        }
        #pragma unroll
        for (int rb = 0; rb < 2; rb++){
            int r = rowx + rb*64;
            float4 v; v.x = a0[rb][0]; v.y = a0[rb][1]; v.z = a0[rb][2]; v.w = a0[rb][3];
            *(float4*)&sxe[r*20 + fg] = v;
        }
    }

    // y_embed -> bf16 global
    {
        int rowy = tid >> 3, ob = (tid & 7) * 8;
        float4 acc0[4], acc1[4];
        float4 bias0 = *(const float4*)&swb[ob];
        float4 bias1 = *(const float4*)&swb[ob + 4];
        #pragma unroll
        for (int blk = 0; blk < 4; blk++){ acc0[blk] = bias0; acc1[blk] = bias1; }
        #pragma unroll 4
        for (int c = 0; c < 64; c++){
            float4 w0 = *(const float4*)&swa[c*64 + ob];
            float4 w1 = *(const float4*)&swa[c*64 + ob + 4];
            #pragma unroll
            for (int blk = 0; blk < 4; blk++){
                float xv = sx[(rowy + blk*32 + 1)*65 + c];
                acc0[blk].x = fmaf(xv, w0.x, acc0[blk].x);
                acc0[blk].y = fmaf(xv, w0.y, acc0[blk].y);
                acc0[blk].z = fmaf(xv, w0.z, acc0[blk].z);
                acc0[blk].w = fmaf(xv, w0.w, acc0[blk].w);
                acc1[blk].x = fmaf(xv, w1.x, acc1[blk].x);
                acc1[blk].y = fmaf(xv, w1.y, acc1[blk].y);
                acc1[blk].z = fmaf(xv, w1.z, acc1[blk].z);
                acc1[blk].w = fmaf(xv, w1.w, acc1[blk].w);
            }
        }
        #pragma unroll
        for (int blk = 0; blk < 4; blk++){
            int r = rowy + blk*32;
            uint4 u;
            u.x = pkbf(acc0[blk].x, acc0[blk].y);
            u.y = pkbf(acc0[blk].z, acc0[blk].w);
            u.z = pkbf(acc1[blk].x, acc1[blk].y);
            u.w = pkbf(acc1[blk].z, acc1[blk].w);
            *(uint4*)&g_ybf[n][l0 + r][ob] = u;
        }
    }
    __syncthreads();

    // hash + norms + normalized bf16 x
    {
        int h = tid >> 6, rowbase = tid & 63;
        const float* Rh = &sR[(h*128)*16];
        #pragma unroll
        for (int rb = 0; rb < 2; rb++){
            int r = rowbase + rb*64;
            int l = l0 + r;
            float4 q0 = *(const float4*)&sxe[r*20 + 0];
            float4 q1 = *(const float4*)&sxe[r*20 + 4];
            float4 q2 = *(const float4*)&sxe[r*20 + 8];
            float4 q3 = *(const float4*)&sxe[r*20 + 12];
            if (h == 0){
                float nn = q0.x*q0.x + q0.y*q0.y + q0.z*q0.z + q0.w*q0.w;
                nn += q1.x*q1.x + q1.y*q1.y + q1.z*q1.z + q1.w*q1.w;
                nn += q2.x*q2.x + q2.y*q2.y + q2.z*q2.z + q2.w*q2.w;
                nn += q3.x*q3.x + q3.y*q3.y + q3.z*q3.z + q3.w*q3.w;
                nn = sqrtf(nn);
                g_xnorm[n][l] = nn;
                float inv = 1.f / fmaxf(nn, 5e-5f);
                uint4 u0, u1;
                u0.x = pkbf(q0.x*inv, q0.y*inv); u0.y = pkbf(q0.z*inv, q0.w*inv);
                u0.z = pkbf(q1.x*inv, q1.y*inv); u0.w = pkbf(q1.z*inv, q1.w*inv);
                u1.x = pkbf(q2.x*inv, q2.y*inv); u1.y = pkbf(q2.z*inv, q2.w*inv);
                u1.z = pkbf(q3.x*inv, q3.y*inv); u1.w = pkbf(q3.z*inv, q3.w*inv);
                *(uint4*)&g_xbf[n][l][0] = u0;
                *(uint4*)&g_xbf[n][l][8] = u1;
            }
            float m1 = -1e30f, m2 = 1e30f; int i1 = 0, i2 = 0;
            #pragma unroll 2
            for (int i = 0; i < 128; i++){
                float4 r0 = *(const float4*)&Rh[i*16 + 0];
                float4 r1 = *(const float4*)&Rh[i*16 + 4];
                float4 r2 = *(const float4*)&Rh[i*16 + 8];
                float4 r3 = *(const float4*)&Rh[i*16 + 12];
                float v = q0.x*r0.x + q0.y*r0.y + q0.z*r0.z + q0.w*r0.w;
                v += q1.x*r1.x + q1.y*r1.y + q1.z*r1.z + q1.w*r1.w;
                v += q2.x*r2.x + q2.y*r2.y + q2.z*r2.z + q2.w*r2.w;
                v += q3.x*r3.x + q3.y*r3.y + q3.z*r3.z + q3.w*r3.w;
                if (v > m1){ m1 = v; i1 = i; }
                if (v < m2){ m2 = v; i2 = i; }
            }
            int code = ((m1 >= -m2) ? i1 : (HB + i2)) + h*HB;
            int j = h*LSEQ + l;
            g_codes[n][j] = code;
            atomicAdd(&g_tileHist[n][j >> 9][code], 1);
        }
    }
}

// ---------------- K1: tile-prefix + key base (UNCHANGED) ----------------
__global__ void k_scan(){
    __shared__ int stot[NKEY];
    __shared__ int sc[1024];
    int n = blockIdx.x; int k = threadIdx.x;
    if (k < NKEY){
        int run = 0;
        #pragma unroll 4
        for (int tl = 0; tl < NTILE; tl++){
            int v = g_tileHist[n][tl][k];
            g_tileHist[n][tl][k] = run;
            run += v;
        }
        stot[k] = run;
    }
    __syncthreads();
    int v0 = (k < NKEY) ? stot[k] : 0;
    sc[k] = v0;
    __syncthreads();
    #pragma unroll
    for (int off = 1; off < 1024; off <<= 1){
        int add = (k >= off) ? sc[k-off] : 0;
        __syncthreads();
        sc[k] += add;
        __syncthreads();
    }
    if (k < NKEY) g_keyBase[n][k] = sc[k] - v0;
}

// ---------------- K2: stable scatter (UNCHANGED) ----------------
__global__ void k_scatter(){
    __shared__ int skey[TILE];
    int b = blockIdx.x; int n = b >> 7, tl = b & 127;
    int t = threadIdx.x;
    int key = g_codes[n][tl*TILE + t];
    skey[t] = key;
    __syncthreads();
    int r = 0;
    for (int u = 0; u < TILE; u++){
        int ku = skey[u];
        if (u < t && ku == key) r++;
    }
    int pos = g_keyBase[n][key] + g_tileHist[n][tl][key] + r;
    g_perm[n][pos] = tl*TILE + t;
}

// ---------------- K3: chunked attention, coalesced bf16 staging + ldmatrix ----------------
// smem (uint32 words):
//   sK  [128][12]  (K/Q rows, bf16x2 words, 32B data + pad)    = 1536
//   sV  [128][36]  (V rows row-major bf16, 128B data + 16B pad)= 4608
//   sL  [128] int, sM2 [128] float, sJ [128] int
#define A3_SK  0
#define A3_SV  1536
#define A3_SL  (1536+4608)
#define A3_SM2 (1536+4608+128)
#define A3_SJ  (1536+4608+256)
#define SMEM_ATTN ((A3_SJ+128)*4)

__global__ void __launch_bounds__(128,4) k_attn(){
    extern __shared__ uint32 smw[];
    uint32* sK  = smw + A3_SK;
    uint32* sV  = smw + A3_SV;
    int*    sL  = (int*)(smw + A3_SL);
    float*  sM2 = (float*)(smw + A3_SM2);
    int*    sJ  = (int*)(smw + A3_SJ);

    int cid = blockIdx.x;
    int n = cid >> 9, rem = cid & 511;
    int g = rem >> 7, k = rem & 127;
    int tid = threadIdx.x;
    int lane = tid & 31, w = tid >> 5;
    int g4 = lane >> 2, t4 = lane & 3;
    int rbase = w*32;

    // ldmatrix per-lane base address (bytes, shared space)
    uint32 svbyte = (uint32)__cvta_generic_to_shared(sV);
    int lr8 = lane & 7, grp = lane >> 3;
    uint32 ld_base = svbyte + (uint32)(((grp & 1)*8 + lr8) * 144 + (grp >> 1) * 16);

    uint32 qf[2][4];
    float m2lo[2], m2hi[2];
    float o[2][8][4];
    #pragma unroll
    for (int rt = 0; rt < 2; rt++)
        #pragma unroll
        for (int ct = 0; ct < 8; ct++)
            #pragma unroll
            for (int u = 0; u < 4; u++) o[rt][ct][u] = 0.f;
    float rs0[2] = {0.f, 0.f}, rs1[2] = {0.f, 0.f};

    #pragma unroll
    for (int pass = 0; pass < 3; pass++){
        int kc = (pass == 0) ? k : (pass == 1) ? ((k + 127) & 127) : ((k + 1) & 127);
        __syncthreads();   // protect tiles/sL from overwrite while mainloop of prev pass runs
        {
            int p = (g << 14) + (kc << 7) + tid;
            int j = g_perm[n][p];
            int l = j & (LSEQ - 1);
            sL[tid] = l;
            if (pass == 0){
                sJ[tid] = j;
                sM2[tid] = g_xnorm[n][l] * LOG2E;
            }
        }
        __syncthreads();
        // cooperative K copy: 2 threads per row (16B each), 2 iters
        {
            int row = tid >> 1, off = tid & 1;
            #pragma unroll
            for (int it = 0; it < 2; it++){
                int r = row + it*64;
                uint4 v = *(const uint4*)&g_xbf[n][sL[r]][off*8];
                *(uint4*)&sK[r*12 + off*4] = v;
            }
        }
        // cooperative V copy: 8 threads per row (16B each), 8 iters
        {
            int row = tid >> 3, off = tid & 7;
            #pragma unroll
            for (int it = 0; it < 8; it++){
                int r = row + it*16;
                uint4 v = *(const uint4*)&g_ybf[n][sL[r]][off*8];
                *(uint4*)&sV[r*36 + off*4] = v;
            }
        }
        __syncthreads();
        if (pass == 0){
            #pragma unroll
            for (int rt = 0; rt < 2; rt++){
                int row = rbase + rt*16 + g4;
                qf[rt][0] = sK[row*12 + t4];
                qf[rt][1] = sK[(row+8)*12 + t4];
                qf[rt][2] = sK[row*12 + 4 + t4];
                qf[rt][3] = sK[(row+8)*12 + 4 + t4];
                m2lo[rt] = sM2[row];
                m2hi[rt] = sM2[row+8];
            }
        }

        for (int nt = 0; nt < 8; nt++){
            uint32 kb[2][2];
            #pragma unroll
            for (int h = 0; h < 2; h++){
                int key = nt*16 + h*8 + g4;
                kb[h][0] = sK[key*12 + t4];
                kb[h][1] = sK[key*12 + 4 + t4];
            }
            float sc2[2][2][4];
            #pragma unroll
            for (int rt = 0; rt < 2; rt++)
                #pragma unroll
                for (int h = 0; h < 2; h++){
                    sc2[rt][h][0] = 0.f; sc2[rt][h][1] = 0.f;
                    sc2[rt][h][2] = 0.f; sc2[rt][h][3] = 0.f;
                    mma16816(sc2[rt][h], qf[rt], kb[h][0], kb[h][1]);
                }
            uint32 pf[2][4];
            #pragma unroll
            for (int rt = 0; rt < 2; rt++){
                #pragma unroll
                for (int h = 0; h < 2; h++){
                    float e0 = ex2a(fmaf(sc2[rt][h][0], m2lo[rt], -m2lo[rt]));
                    float e1 = ex2a(fmaf(sc2[rt][h][1], m2lo[rt], -m2lo[rt]));
                    float e2 = ex2a(fmaf(sc2[rt][h][2], m2hi[rt], -m2hi[rt]));
                    float e3 = ex2a(fmaf(sc2[rt][h][3], m2hi[rt], -m2hi[rt]));
                    rs0[rt] += e0 + e1;
                    rs1[rt] += e2 + e3;
                    pf[rt][h*2]   = pkbf(e0, e1);
                    pf[rt][h*2+1] = pkbf(e2, e3);
                }
            }
            uint32 vaddr = ld_base + (uint32)(nt * 16 * 144);
            #pragma unroll
            for (int q = 0; q < 4; q++){
                uint32 v0, v1, v2, v3;
                ldsm4t(v0, v1, v2, v3, vaddr + q*32);
                mma16816(o[0][2*q],   pf[0], v0, v1);
                mma16816(o[1][2*q],   pf[1], v0, v1);
                mma16816(o[0][2*q+1], pf[0], v2, v3);
                mma16816(o[1][2*q+1], pf[1], v2, v3);
            }
        }
    }

    // ---- epilogue ----
    #pragma unroll
    for (int rt = 0; rt < 2; rt++){
        float v0 = rs0[rt];
        v0 += __shfl_xor_sync(0xffffffffu, v0, 1);
        v0 += __shfl_xor_sync(0xffffffffu, v0, 2);
        float v1 = rs1[rt];
        v1 += __shfl_xor_sync(0xffffffffu, v1, 1);
        v1 += __shfl_xor_sync(0xffffffffu, v1, 2);
        float i0 = 1.f / v0, i1 = 1.f / v1;
        int row0 = rbase + rt*16 + g4, row1 = row0 + 8;
        int j0 = sJ[row0], j1 = sJ[row1];
        if (t4 == 0){
            g_bs[n][j0] = (sM2[row0] + lg2a(v0)) * LN2;
            g_bs[n][j1] = (sM2[row1] + lg2a(v1)) * LN2;
        }
        unsigned short* r0p = &g_ret[n][j0][0];
        unsigned short* r1p = &g_ret[n][j1][0];
        #pragma unroll
        for (int ct = 0; ct < 8; ct++){
            int ch = ct*8 + 2*t4;
            *(uint32*)&r0p[ch] = pkbf(o[rt][ct][0]*i0, o[rt][ct][1]*i0);
            *(uint32*)&r1p[ch] = pkbf(o[rt][ct][2]*i1, o[rt][ct][3]*i1);
        }
    }
}

// ---------------- K4: combine + residual + hist re-zero (UNCHANGED) ----------------
__global__ void k_combine(const float* __restrict__ x, float* __restrict__ out){
    int gt = blockIdx.x * 256 + threadIdx.x;
    int n = gt >> 14, l = gt & (LSEQ - 1);
    float b0 = g_bs[n][l];
    float b1 = g_bs[n][LSEQ + l];
    float b2 = g_bs[n][2*LSEQ + l];
    float b3 = g_bs[n][3*LSEQ + l];
    float mx = fmaxf(fmaxf(b0, b1), fmaxf(b2, b3));
    float e0 = ex2a((b0 - mx)*LOG2E), e1 = ex2a((b1 - mx)*LOG2E);
    float e2 = ex2a((b2 - mx)*LOG2E), e3 = ex2a((b3 - mx)*LOG2E);
    float inv = 1.f / (e0 + e1 + e2 + e3);
    float p0 = e0*inv, p1 = e1*inv, p2 = e2*inv, p3 = e3*inv;

    const uint4* r0 = (const uint4*)&g_ret[n][l][0];
    const uint4* r1 = (const uint4*)&g_ret[n][LSEQ + l][0];
    const uint4* r2 = (const uint4*)&g_ret[n][2*LSEQ + l][0];
    const uint4* r3 = (const uint4*)&g_ret[n][3*LSEQ + l][0];
    const float4* x4 = (const float4*)&x[((size_t)n*LSEQ + l)*64];
    float4* o4 = (float4*)&out[((size_t)n*LSEQ + l)*64];
    #pragma unroll
    for (int t = 0; t < 8; t++){
        uint4 u0 = r0[t], u1 = r1[t], u2 = r2[t], u3 = r3[t];
        float4 xa = x4[2*t], xb = x4[2*t+1];
        float4 oa, ob;
        oa.x = xa.x + p0*blo(u0.x) + p1*blo(u1.x) + p2*blo(u2.x) + p3*blo(u3.x);
        oa.y = xa.y + p0*bhi(u0.x) + p1*bhi(u1.x) + p2*bhi(u2.x) + p3*bhi(u3.x);
        oa.z = xa.z + p0*blo(u0.y) + p1*blo(u1.y) + p2*blo(u2.y) + p3*blo(u3.y);
        oa.w = xa.w + p0*bhi(u0.y) + p1*bhi(u1.y) + p2*bhi(u2.y) + p3*bhi(u3.y);
        ob.x = xb.x + p0*blo(u0.z) + p1*blo(u1.z) + p2*blo(u2.z) + p3*blo(u3.z);
        ob.y = xb.y + p0*bhi(u0.z) + p1*bhi(u1.z) + p2*bhi(u2.z) + p3*bhi(u3.z);
        ob.z = xb.z + p0*blo(u0.w) + p1*blo(u1.w) + p2*blo(u2.w) + p3*blo(u3.w);
        ob.w = xb.w + p0*bhi(u0.w) + p1*bhi(u1.w) + p2*bhi(u2.w) + p3*bhi(u3.w);
        o4[2*t] = oa;
        o4[2*t+1] = ob;
    }
    int* hist = &g_tileHist[0][0][0];
    const int tot = NB*NTILE*NKEY;
    for (int idx = gt; idx < tot; idx += NB*LSEQ) hist[idx] = 0;
}

// ---------------- launch ----------------
extern "C" void kernel_launch(void* const* d_in, const int* in_sizes, int n_in,
                              void* d_out, int out_size){
    const float* x  = (const float*)d_in[0];
    const float* wm = (const float*)d_in[1];
    const float* wa = (const float*)d_in[2];
    const float* wb = (const float*)d_in[3];
    const float* rt = (const float*)d_in[4];
    float* out = (float*)d_out;

    static bool attr_done = false;
    if (!attr_done){
        cudaFuncSetAttribute(k_ehh, cudaFuncAttributeMaxDynamicSharedMemorySize, SMEM_EHH);
        attr_done = true;
    }

    k_ehh    <<<NB*(LSEQ/TL2), 256, SMEM_EHH>>>(x, wm, wa, wb, rt);
    k_scan   <<<NB, 1024>>>();
    k_scatter<<<NB*NTILE, TILE>>>();
    k_attn   <<<NB*NH*KCH, 128, SMEM_ATTN>>>();
    k_combine<<<(NB*LSEQ)/256, 256>>>(x, out);
}